// round 4
// baseline (speedup 1.0000x reference)
#include <cuda_runtime.h>
#include <math.h>

#define B_ 2
#define T_ 2048
#define C_ 768
#define H_ 12
#define D_ 64
#define M_ (B_*T_)   // 4096

// Scratch (allocation-free rule: __device__ globals)
__device__ float g_q[B_*H_*T_*D_];
__device__ float g_k[B_*H_*T_*D_];
__device__ float g_v[B_*H_*T_*D_];
__device__ float g_att[B_*T_*C_];

// ---------------------------------------------------------------------------
// Kernel 1: qkv = x @ Wqkv  (M=4096, K=768, N=2304), scatter into [B,H,T,DH]
// ---------------------------------------------------------------------------
__global__ __launch_bounds__(256) void qkv_gemm_kernel(const float* __restrict__ x,
                                                       const float* __restrict__ W) {
    __shared__ float As[16][64];   // A^T tile
    __shared__ float Bs[16][64];
    const int tid = threadIdx.x;
    const int tx = tid & 15, ty = tid >> 4;
    const int m0 = blockIdx.y * 64;
    const int n0 = blockIdx.x * 64;
    const int a_row = tid >> 2, a_k = (tid & 3) * 4;
    const int b_k = tid >> 4, b_n = (tid & 15) * 4;
    float acc[4][4] = {};
    for (int k0 = 0; k0 < C_; k0 += 16) {
        float4 av = *(const float4*)&x[(m0 + a_row) * C_ + k0 + a_k];
        As[a_k+0][a_row] = av.x;
        As[a_k+1][a_row] = av.y;
        As[a_k+2][a_row] = av.z;
        As[a_k+3][a_row] = av.w;
        *(float4*)&Bs[b_k][b_n] = *(const float4*)&W[(k0 + b_k) * (3*C_) + n0 + b_n];
        __syncthreads();
#pragma unroll
        for (int kk = 0; kk < 16; kk++) {
            float4 a  = *(float4*)&As[kk][ty*4];
            float4 bv = *(float4*)&Bs[kk][tx*4];
            float ar[4] = {a.x, a.y, a.z, a.w};
            float br[4] = {bv.x, bv.y, bv.z, bv.w};
#pragma unroll
            for (int i = 0; i < 4; i++)
#pragma unroll
                for (int j = 0; j < 4; j++)
                    acc[i][j] = fmaf(ar[i], br[j], acc[i][j]);
        }
        __syncthreads();
    }
    // Scatter: whole block lies in exactly one of q/k/v (boundaries at 768/1536)
    float* dst; int nrel0;
    if (n0 < C_)          { dst = g_q; nrel0 = n0; }
    else if (n0 < 2*C_)   { dst = g_k; nrel0 = n0 - C_; }
    else                  { dst = g_v; nrel0 = n0 - 2*C_; }
#pragma unroll
    for (int i = 0; i < 4; i++) {
        int m = m0 + ty*4 + i;
        int b = m >> 11, t = m & (T_-1);
#pragma unroll
        for (int j = 0; j < 4; j++) {
            int nrel = nrel0 + tx*4 + j;
            int h = nrel >> 6, d = nrel & 63;
            dst[((b*H_ + h)*T_ + t)*D_ + d] = acc[i][j];
        }
    }
}

// ---------------------------------------------------------------------------
// Kernel 2: causal flash attention, Br=Bc=64, fp32, online softmax.
// Grid: (32 q-tiles, B*H). Heavy q-tiles launched first (qt = 31 - blockIdx.x).
// ---------------------------------------------------------------------------
__global__ __launch_bounds__(256) void attn_kernel() {
    extern __shared__ float sm[];
    float* Qt = sm;                  // [64][65]  Q transposed (d-major)
    float* Kt = Qt + 64*65;          // [64][65]  K transposed
    float* Pt = Kt + 64*65;          // [64][65]  P transposed (j-major)
    float* Vs = Pt + 64*65;          // [64][64]  V direct

    const int tid = threadIdx.x;
    const int tx = tid & 15, ty = tid >> 4;
    const int bh = blockIdx.y;
    const int b = bh / H_, h = bh % H_;
    const int qt = (gridDim.x - 1) - blockIdx.x;   // descending workload

    const float* qb  = g_q + ((b*H_ + h)*T_ + qt*64) * D_;
    const float* kb0 = g_k + ((b*H_ + h)*T_) * D_;
    const float* vb0 = g_v + ((b*H_ + h)*T_) * D_;

    // Load Q tile transposed
    for (int it = tid; it < 64*16; it += 256) {
        int r = it >> 4, dq = (it & 15) << 2;
        float4 v4 = *(const float4*)&qb[r*64 + dq];
        Qt[(dq+0)*65 + r] = v4.x;
        Qt[(dq+1)*65 + r] = v4.y;
        Qt[(dq+2)*65 + r] = v4.z;
        Qt[(dq+3)*65 + r] = v4.w;
    }

    float m_r[4], l_r[4], o[4][4];
#pragma unroll
    for (int i = 0; i < 4; i++) {
        m_r[i] = -INFINITY; l_r[i] = 0.f;
#pragma unroll
        for (int j = 0; j < 4; j++) o[i][j] = 0.f;
    }

    const float scale = 0.125f;  // DH^-0.5

    for (int kt = 0; kt <= qt; kt++) {
        __syncthreads();  // previous iter done reading Kt/Vs/Pt; Qt load done (iter 0)
        const float* kb = kb0 + kt*64*D_;
        const float* vb = vb0 + kt*64*D_;
        for (int it = tid; it < 64*16; it += 256) {
            int r = it >> 4, dq = (it & 15) << 2;
            float4 v4 = *(const float4*)&kb[r*64 + dq];
            Kt[(dq+0)*65 + r] = v4.x;
            Kt[(dq+1)*65 + r] = v4.y;
            Kt[(dq+2)*65 + r] = v4.z;
            Kt[(dq+3)*65 + r] = v4.w;
            *(float4*)&Vs[r*64 + dq] = *(const float4*)&vb[r*64 + dq];
        }
        __syncthreads();

        // S = Q K^T
        float s[4][4] = {};
#pragma unroll 4
        for (int d = 0; d < 64; d++) {
            float qv[4], kv[4];
#pragma unroll
            for (int i = 0; i < 4; i++) qv[i] = Qt[d*65 + ty*4 + i];
#pragma unroll
            for (int j = 0; j < 4; j++) kv[j] = Kt[d*65 + tx*4 + j];
#pragma unroll
            for (int i = 0; i < 4; i++)
#pragma unroll
                for (int j = 0; j < 4; j++)
                    s[i][j] = fmaf(qv[i], kv[j], s[i][j]);
        }

        if (kt == qt) {
#pragma unroll
            for (int i = 0; i < 4; i++) {
                int r = ty*4 + i;
#pragma unroll
                for (int j = 0; j < 4; j++) {
                    int c = tx*4 + j;
                    s[i][j] = (c <= r) ? s[i][j]*scale : -INFINITY;
                }
            }
        } else {
#pragma unroll
            for (int i = 0; i < 4; i++)
#pragma unroll
                for (int j = 0; j < 4; j++) s[i][j] *= scale;
        }

        // Online softmax per row; row-reduce over 16 tx lanes via shfl.bfly
#pragma unroll
        for (int i = 0; i < 4; i++) {
            float rmax = fmaxf(fmaxf(s[i][0], s[i][1]), fmaxf(s[i][2], s[i][3]));
#pragma unroll
            for (int off = 8; off >= 1; off >>= 1)
                rmax = fmaxf(rmax, __shfl_xor_sync(0xffffffffu, rmax, off));
            float mnew = fmaxf(m_r[i], rmax);
            float corr = __expf(m_r[i] - mnew);
            float p[4], psum = 0.f;
#pragma unroll
            for (int j = 0; j < 4; j++) { p[j] = __expf(s[i][j] - mnew); psum += p[j]; }
#pragma unroll
            for (int off = 8; off >= 1; off >>= 1)
                psum += __shfl_xor_sync(0xffffffffu, psum, off);
            l_r[i] = l_r[i] * corr + psum;
            m_r[i] = mnew;
#pragma unroll
            for (int j = 0; j < 4; j++) o[i][j] *= corr;
#pragma unroll
            for (int j = 0; j < 4; j++)
                Pt[(tx*4 + j)*65 + ty*4 + i] = p[j];
        }
        __syncthreads();

        // O += P @ V
#pragma unroll 4
        for (int jx = 0; jx < 64; jx++) {
            float pv[4];
#pragma unroll
            for (int i = 0; i < 4; i++) pv[i] = Pt[jx*65 + ty*4 + i];
            float4 v4 = *(float4*)&Vs[jx*64 + tx*4];
            float vv[4] = {v4.x, v4.y, v4.z, v4.w};
#pragma unroll
            for (int i = 0; i < 4; i++)
#pragma unroll
                for (int j = 0; j < 4; j++)
                    o[i][j] = fmaf(pv[i], vv[j], o[i][j]);
        }
    }

    // Epilogue: normalize and write in [B,T,C] layout for the output GEMM
#pragma unroll
    for (int i = 0; i < 4; i++) {
        float inv = 1.f / l_r[i];
        int r = qt*64 + ty*4 + i;
        float4 ov;
        ov.x = o[i][0]*inv; ov.y = o[i][1]*inv; ov.z = o[i][2]*inv; ov.w = o[i][3]*inv;
        *(float4*)&g_att[(b*T_ + r)*C_ + h*64 + tx*4] = ov;
    }
}

// ---------------------------------------------------------------------------
// Kernel 3: out = att @ Wout  (M=4096, K=768, N=768)
// ---------------------------------------------------------------------------
__global__ __launch_bounds__(256) void out_gemm_kernel(const float* __restrict__ W,
                                                       float* __restrict__ out) {
    __shared__ float As[16][64];
    __shared__ float Bs[16][64];
    const int tid = threadIdx.x;
    const int tx = tid & 15, ty = tid >> 4;
    const int m0 = blockIdx.y * 64;
    const int n0 = blockIdx.x * 64;
    const int a_row = tid >> 2, a_k = (tid & 3) * 4;
    const int b_k = tid >> 4, b_n = (tid & 15) * 4;
    float acc[4][4] = {};
    for (int k0 = 0; k0 < C_; k0 += 16) {
        float4 av = *(const float4*)&g_att[(m0 + a_row) * C_ + k0 + a_k];
        As[a_k+0][a_row] = av.x;
        As[a_k+1][a_row] = av.y;
        As[a_k+2][a_row] = av.z;
        As[a_k+3][a_row] = av.w;
        *(float4*)&Bs[b_k][b_n] = *(const float4*)&W[(k0 + b_k) * C_ + n0 + b_n];
        __syncthreads();
#pragma unroll
        for (int kk = 0; kk < 16; kk++) {
            float4 a  = *(float4*)&As[kk][ty*4];
            float4 bv = *(float4*)&Bs[kk][tx*4];
            float ar[4] = {a.x, a.y, a.z, a.w};
            float br[4] = {bv.x, bv.y, bv.z, bv.w};
#pragma unroll
            for (int i = 0; i < 4; i++)
#pragma unroll
                for (int j = 0; j < 4; j++)
                    acc[i][j] = fmaf(ar[i], br[j], acc[i][j]);
        }
        __syncthreads();
    }
#pragma unroll
    for (int i = 0; i < 4; i++) {
        int m = m0 + ty*4 + i;
        float4 ov;
        ov.x = acc[i][0]; ov.y = acc[i][1]; ov.z = acc[i][2]; ov.w = acc[i][3];
        *(float4*)&out[m * C_ + n0 + tx*4] = ov;
    }
}

// ---------------------------------------------------------------------------
extern "C" void kernel_launch(void* const* d_in, const int* in_sizes, int n_in,
                              void* d_out, int out_size) {
    const float* x    = (const float*)d_in[0];
    const float* Wqkv = (const float*)d_in[1];
    const float* Wout = (const float*)d_in[2];
    float* out = (float*)d_out;

    // QKV projection
    {
        dim3 grid(3*C_/64, M_/64);   // (36, 64)
        qkv_gemm_kernel<<<grid, 256>>>(x, Wqkv);
    }
    // Flash attention
    {
        const int smem_bytes = (3*64*65 + 64*64) * (int)sizeof(float);  // 66304
        cudaFuncSetAttribute(attn_kernel, cudaFuncAttributeMaxDynamicSharedMemorySize,
                             smem_bytes);
        dim3 grid(T_/64, B_*H_);     // (32, 24)
        attn_kernel<<<grid, 256, smem_bytes>>>();
    }
    // Output projection
    {
        dim3 grid(C_/64, M_/64);     // (12, 64)
        out_gemm_kernel<<<grid, 256>>>(Wout, out);
    }
}